// round 17
// baseline (speedup 1.0000x reference)
#include <cuda_runtime.h>
#include <cuda_bf16.h>

#define D 128
#define MAXN 100000
#define MAXE 1600000
#define RPSTRIDE (MAXN + 4)   // rowptr per-graph stride, 16B-aligned
#define XSP 132               // float row stride for X tile (132*4=528B, 16B-aligned rows)

typedef unsigned long long ull;
typedef unsigned int uint;

// ---------------- device scratch, duplicated per graph (no allocations) ----------------
__device__ int   g_cnt[2][MAXN];
__device__ int   g_rowptr[2][RPSTRIDE];
__device__ int   g_cursor[2][MAXN];
__device__ int   g_csr[2][MAXE];
__device__ float g_dinv[2][MAXN];
__device__ int   g_bsum[2][128];
__device__ int   g_boff[2][128];
__device__ float g_h[2][(size_t)MAXN * D];          // dense output, fp32
__device__ uint  g_hb[2][(size_t)MAXN * (D / 2)];   // dense output, packed bf16x2
__device__ float g_x[2][(size_t)MAXN * D];          // layer-1 activation

// ---------------- packed f32x2 helpers ----------------
__device__ __forceinline__ ull pack2(float x, float y) {
    ull r;
    asm("mov.b64 %0, {%1, %2};" : "=l"(r) : "f"(x), "f"(y));
    return r;
}
__device__ __forceinline__ void unpack2(ull v, float& x, float& y) {
    asm("mov.b64 {%0, %1}, %2;" : "=f"(x), "=f"(y) : "l"(v));
}
__device__ __forceinline__ void ffma2(ull& acc, ull a, ull b) {
    asm("fma.rn.f32x2 %0, %1, %2, %0;" : "+l"(acc) : "l"(a), "l"(b));
}
__device__ __forceinline__ void bf2x(uint v, float& lo, float& hi) {
    lo = __uint_as_float(v << 16);
    hi = __uint_as_float(v & 0xffff0000u);
}
__device__ __forceinline__ void lds_v2u64(ull& a, ull& b, const void* p) {
    asm volatile("ld.shared.v2.u64 {%0, %1}, [%2];" : "=l"(a), "=l"(b) : "l"(__cvta_generic_to_shared(p)));
}
__device__ __forceinline__ void lds_f4(float& a, float& b, float& c, float& d, const void* p) {
    asm volatile("ld.shared.v4.f32 {%0, %1, %2, %3}, [%4];"
                 : "=f"(a), "=f"(b), "=f"(c), "=f"(d) : "l"(__cvta_generic_to_shared(p)));
}

// ---------------- CSR build ----------------
__global__ void zero_cnt_k(int* __restrict__ cnt, int n) {
    int i = blockIdx.x * blockDim.x + threadIdx.x;
    if (i < n) cnt[i] = 0;
}

__global__ void count_k(const int* __restrict__ dst, int* __restrict__ cnt, int E) {
    int i = blockIdx.x * blockDim.x + threadIdx.x;
    if (i < E) atomicAdd(&cnt[dst[i]], 1);
}

__global__ void scan1_k(const int* __restrict__ cnt, int* __restrict__ rowptr,
                        int* __restrict__ bsum, int n) {
    __shared__ int wsum[8];
    int tid = threadIdx.x, lane = tid & 31, warp = tid >> 5;
    int base = blockIdx.x * 1024 + tid * 4;
    int4 v = make_int4(0, 0, 0, 0);
    if (base + 3 < n) {
        v = *(const int4*)(cnt + base);
    } else {
        if (base + 0 < n) v.x = cnt[base + 0];
        if (base + 1 < n) v.y = cnt[base + 1];
        if (base + 2 < n) v.z = cnt[base + 2];
    }
    int s = v.x + v.y + v.z + v.w;
    int t = s;
    #pragma unroll
    for (int o = 1; o < 32; o <<= 1) {
        int u = __shfl_up_sync(0xffffffffu, t, o);
        if (lane >= o) t += u;
    }
    if (lane == 31) wsum[warp] = t;
    __syncthreads();
    if (warp == 0 && lane < 8) {
        int w = wsum[lane];
        #pragma unroll
        for (int o = 1; o < 8; o <<= 1) {
            int u = __shfl_up_sync(0xffu, w, o);
            if (lane >= o) w += u;
        }
        wsum[lane] = w;
    }
    __syncthreads();
    int excl = t - s + (warp ? wsum[warp - 1] : 0);
    int p0 = excl, p1 = p0 + v.x, p2 = p1 + v.y, p3 = p2 + v.z;
    if (base + 3 < n) {
        *(int4*)(rowptr + base) = make_int4(p0, p1, p2, p3);
    } else {
        if (base + 0 < n) rowptr[base + 0] = p0;
        if (base + 1 < n) rowptr[base + 1] = p1;
        if (base + 2 < n) rowptr[base + 2] = p2;
    }
    if (tid == 255) bsum[blockIdx.x] = excl + s;
}

__global__ void scan2_k(const int* __restrict__ bsum, int* __restrict__ boff,
                        int* __restrict__ rowptr, int n, int nb) {
    __shared__ int wsum[4];
    int tid = threadIdx.x, lane = tid & 31, warp = tid >> 5;
    int v = (tid < nb) ? bsum[tid] : 0;
    int t = v;
    #pragma unroll
    for (int o = 1; o < 32; o <<= 1) {
        int u = __shfl_up_sync(0xffffffffu, t, o);
        if (lane >= o) t += u;
    }
    if (lane == 31) wsum[warp] = t;
    __syncthreads();
    if (warp == 0 && lane < 4) {
        int w = wsum[lane];
        #pragma unroll
        for (int o = 1; o < 4; o <<= 1) {
            int u = __shfl_up_sync(0xfu, w, o);
            if (lane >= o) w += u;
        }
        wsum[lane] = w;
    }
    __syncthreads();
    int excl = t - v + (warp ? wsum[warp - 1] : 0);
    if (tid < nb) boff[tid] = excl;
    if (tid == 127) rowptr[n] = wsum[3];
}

__global__ void scan3_k(const int* __restrict__ cnt, const int* __restrict__ boff,
                        int* __restrict__ rowptr, int* __restrict__ cursor,
                        float* __restrict__ dinv, int n) {
    int i = blockIdx.x * blockDim.x + threadIdx.x;
    if (i < n) {
        int rp = rowptr[i] + boff[i >> 10];
        rowptr[i] = rp;
        cursor[i] = rp;
        dinv[i] = rsqrtf((float)(cnt[i] + 1));
    }
}

__global__ void fill_k(const int* __restrict__ src, const int* __restrict__ dst,
                       int* __restrict__ cursor, int* __restrict__ csr, int E) {
    int i = blockIdx.x * blockDim.x + threadIdx.x;
    if (i < E) {
        int p = atomicAdd(&cursor[dst[i]], 1);
        csr[p] = src[i];
    }
}

// ---------------- dense transform: h/hb = X @ W ----------------
// 64 rows/CTA, 256 threads (8 warps). Warp w: rows w*8..w*8+7 (warp-uniform).
// Lane l: cols 4l..4l+3. k-step = 4: X via one ld.shared.v4.f32 per row
// (crossbar 6 wf/warp/k < FMA floor); W one LDS.128 per k (zero duplication).
__global__ __launch_bounds__(256, 2) void gemm64_k(const float* __restrict__ X,
                                                   const float* __restrict__ W,
                                                   float* __restrict__ h,
                                                   uint* __restrict__ hbuf, int n) {
    extern __shared__ char sm[];
    float4* sW4 = (float4*)sm;                 // [k*32 + c4] : 64KB
    float*  sX  = (float*)(sm + 65536);        // [r*XSP + k] plain : 33.8KB
    int tid = threadIdx.x;
    int row0 = blockIdx.x * 64;

    const float4* W4 = (const float4*)W;
    for (int i = tid; i < D * 32; i += 256) sW4[i] = W4[i];

    for (int i = tid; i < 64 * 32; i += 256) {
        int r = i >> 5, q = i & 31;
        int row = min(row0 + r, n - 1);
        float4 v = ((const float4*)X)[(size_t)row * 32 + q];
        float* xp = sX + r * XSP + q * 4;
        xp[0] = v.x; xp[1] = v.y; xp[2] = v.z; xp[3] = v.w;
    }
    __syncthreads();

    int lane = tid & 31, wid = tid >> 5;
    const float* xb = sX + (wid * 8) * XSP;

    ull acc[8][2] = {};          // [row r][col pair]

    #pragma unroll 2
    for (int k4 = 0; k4 < D; k4 += 4) {
        ull w0a, w0b, w1a, w1b, w2a, w2b, w3a, w3b;
        lds_v2u64(w0a, w0b, sW4 + (k4 + 0) * 32 + lane);
        lds_v2u64(w1a, w1b, sW4 + (k4 + 1) * 32 + lane);
        lds_v2u64(w2a, w2b, sW4 + (k4 + 2) * 32 + lane);
        lds_v2u64(w3a, w3b, sW4 + (k4 + 3) * 32 + lane);
        #pragma unroll
        for (int r = 0; r < 8; r++) {
            float a, b, c, d;
            lds_f4(a, b, c, d, xb + r * XSP + k4);
            ull x0 = pack2(a, a);
            ull x1 = pack2(b, b);
            ull x2 = pack2(c, c);
            ull x3 = pack2(d, d);
            ffma2(acc[r][0], x0, w0a); ffma2(acc[r][1], x0, w0b);
            ffma2(acc[r][0], x1, w1a); ffma2(acc[r][1], x1, w1b);
            ffma2(acc[r][0], x2, w2a); ffma2(acc[r][1], x2, w2b);
            ffma2(acc[r][0], x3, w3a); ffma2(acc[r][1], x3, w3b);
        }
    }

    #pragma unroll
    for (int r = 0; r < 8; r++) {
        int row = row0 + wid * 8 + r;
        if (row < n) {
            ull* hp = (ull*)(h + (size_t)row * D);
            hp[2 * lane]     = acc[r][0];
            hp[2 * lane + 1] = acc[r][1];
            float a, b, c, d2;
            unpack2(acc[r][0], a, b);
            unpack2(acc[r][1], c, d2);
            __nv_bfloat162 p0 = __floats2bfloat162_rn(a, b);
            __nv_bfloat162 p1 = __floats2bfloat162_rn(c, d2);
            ((uint2*)(hbuf + (size_t)row * 64))[lane] =
                make_uint2(*(uint*)&p0, *(uint*)&p1);
        }
    }
}

// ---------------- aggregation: out = relu(agg + h), warp per node ----------------
__global__ void agg_k(float4* __restrict__ out, const float* __restrict__ h,
                      const uint* __restrict__ hbuf, const int* __restrict__ rowptr,
                      const int* __restrict__ csr, const float* __restrict__ dinv, int n) {
    int t = blockIdx.x * blockDim.x + threadIdx.x;
    int node = t >> 5;
    int lane = t & 31;
    if (node >= n) return;

    const float4* h4 = (const float4*)h;
    const uint2*  hb = (const uint2*)hbuf;
    float dv = dinv[node];
    float4 hv = h4[(size_t)node * 32 + lane];
    float ws = dv * dv;
    float4 acc = make_float4(ws * hv.x, ws * hv.y, ws * hv.z, ws * hv.w);

    int s = rowptr[node], e = rowptr[node + 1];
    int i = s;
    for (; i + 3 < e; i += 4) {
        int u0 = csr[i], u1 = csr[i + 1], u2 = csr[i + 2], u3 = csr[i + 3];
        float w0 = dinv[u0] * dv, w1 = dinv[u1] * dv;
        float w2 = dinv[u2] * dv, w3 = dinv[u3] * dv;
        uint2 v0 = hb[(size_t)u0 * 32 + lane];
        uint2 v1 = hb[(size_t)u1 * 32 + lane];
        uint2 v2 = hb[(size_t)u2 * 32 + lane];
        uint2 v3 = hb[(size_t)u3 * 32 + lane];
        float a, b;
        bf2x(v0.x, a, b); acc.x += w0 * a; acc.y += w0 * b;
        bf2x(v0.y, a, b); acc.z += w0 * a; acc.w += w0 * b;
        bf2x(v1.x, a, b); acc.x += w1 * a; acc.y += w1 * b;
        bf2x(v1.y, a, b); acc.z += w1 * a; acc.w += w1 * b;
        bf2x(v2.x, a, b); acc.x += w2 * a; acc.y += w2 * b;
        bf2x(v2.y, a, b); acc.z += w2 * a; acc.w += w2 * b;
        bf2x(v3.x, a, b); acc.x += w3 * a; acc.y += w3 * b;
        bf2x(v3.y, a, b); acc.z += w3 * a; acc.w += w3 * b;
    }
    for (; i < e; i++) {
        int u = csr[i];
        float w = dinv[u] * dv;
        uint2 v = hb[(size_t)u * 32 + lane];
        float a, b;
        bf2x(v.x, a, b); acc.x += w * a; acc.y += w * b;
        bf2x(v.y, a, b); acc.z += w * a; acc.w += w * b;
    }

    out[(size_t)node * 32 + lane] = make_float4(
        fmaxf(acc.x + hv.x, 0.f), fmaxf(acc.y + hv.y, 0.f),
        fmaxf(acc.z + hv.z, 0.f), fmaxf(acc.w + hv.w, 0.f));
}

// ---------------- seed gather: warp per seed ----------------
__global__ void gather_k(const int* __restrict__ seeds, const float4* __restrict__ ent,
                         float4* __restrict__ out, int ns) {
    int t = blockIdx.x * blockDim.x + threadIdx.x;
    int s = t >> 5;
    int lane = t & 31;
    if (s < ns) out[(size_t)s * 32 + lane] = ent[(size_t)seeds[s] * 32 + lane];
}

// ---------------- launch ----------------
static void launch_graph(cudaStream_t st, int g,
                         const int* seeds, const int* edges,
                         const float* emb, const float* W0, const float* W1,
                         float* ent, float* seed_out,
                         int N, int E, int S, int smem) {
    int* cnt;    cudaGetSymbolAddress((void**)&cnt, g_cnt);
    int* rowptr; cudaGetSymbolAddress((void**)&rowptr, g_rowptr);
    int* cursor; cudaGetSymbolAddress((void**)&cursor, g_cursor);
    int* csr;    cudaGetSymbolAddress((void**)&csr, g_csr);
    float* dinv; cudaGetSymbolAddress((void**)&dinv, g_dinv);
    int* bsum;   cudaGetSymbolAddress((void**)&bsum, g_bsum);
    int* boff;   cudaGetSymbolAddress((void**)&boff, g_boff);
    float* h;    cudaGetSymbolAddress((void**)&h, g_h);
    uint* hb;    cudaGetSymbolAddress((void**)&hb, g_hb);
    float* x;    cudaGetSymbolAddress((void**)&x, g_x);
    cnt    += (size_t)g * MAXN;
    rowptr += (size_t)g * RPSTRIDE;
    cursor += (size_t)g * MAXN;
    csr    += (size_t)g * MAXE;
    dinv   += (size_t)g * MAXN;
    bsum   += (size_t)g * 128;
    boff   += (size_t)g * 128;
    h      += (size_t)g * MAXN * D;
    hb     += (size_t)g * MAXN * (D / 2);
    x      += (size_t)g * MAXN * D;

    const int* src = edges;
    const int* dst = edges + E;
    int nb = (N + 1023) / 1024;
    int gtiles = (N + 63) / 64;

    zero_cnt_k<<<(N + 255) / 256, 256, 0, st>>>(cnt, N);
    count_k<<<(E + 255) / 256, 256, 0, st>>>(dst, cnt, E);
    scan1_k<<<nb, 256, 0, st>>>(cnt, rowptr, bsum, N);
    gemm64_k<<<gtiles, 256, smem, st>>>(emb, W0, h, hb, N);
    scan2_k<<<1, 128, 0, st>>>(bsum, boff, rowptr, N, nb);
    scan3_k<<<(N + 255) / 256, 256, 0, st>>>(cnt, boff, rowptr, cursor, dinv, N);
    fill_k<<<(E + 255) / 256, 256, 0, st>>>(src, dst, cursor, csr, E);

    agg_k<<<((size_t)N * 32 + 255) / 256, 256, 0, st>>>((float4*)x, h, hb, rowptr, csr, dinv, N);
    gemm64_k<<<gtiles, 256, smem, st>>>(x, W1, h, hb, N);
    agg_k<<<((size_t)N * 32 + 255) / 256, 256, 0, st>>>((float4*)ent, h, hb, rowptr, csr, dinv, N);
    gather_k<<<((size_t)S * 32 + 255) / 256, 256, 0, st>>>(seeds, (const float4*)ent,
                                                           (float4*)seed_out, S);
}

extern "C" void kernel_launch(void* const* d_in, const int* in_sizes, int n_in,
                              void* d_out, int out_size) {
    const int*   seeds_sr = (const int*)d_in[0];
    const int*   seeds_tg = (const int*)d_in[1];
    const int*   edges_sr = (const int*)d_in[2];
    const int*   edges_tg = (const int*)d_in[3];
    const float* emb_sr   = (const float*)d_in[4];
    const float* emb_tg   = (const float*)d_in[5];
    const float* W0       = (const float*)d_in[6];
    const float* W1       = (const float*)d_in[7];

    int S = in_sizes[0];
    int E = in_sizes[2] / 2;
    int N = in_sizes[4] / D;

    float* out     = (float*)d_out;
    float* sr_seed = out;
    float* tg_seed = sr_seed + (size_t)S * D;
    float* sr_ent  = tg_seed + (size_t)S * D;
    float* tg_ent  = sr_ent  + (size_t)N * D;

    int smem = 65536 + 64 * XSP * 4;   // 64KB W + 33.8KB X = 98.3KB -> 2 CTAs/SM
    static bool inited = false;
    static cudaStream_t s1;
    static cudaEvent_t evFork, evJoin;
    if (!inited) {
        cudaFuncSetAttribute(gemm64_k, cudaFuncAttributeMaxDynamicSharedMemorySize, smem);
        cudaStreamCreateWithFlags(&s1, cudaStreamNonBlocking);
        cudaEventCreateWithFlags(&evFork, cudaEventDisableTiming);
        cudaEventCreateWithFlags(&evJoin, cudaEventDisableTiming);
        inited = true;
    }

    // fork: tg pipeline on side stream, sr pipeline on capture (default) stream
    cudaEventRecord(evFork, 0);
    cudaStreamWaitEvent(s1, evFork, 0);

    launch_graph(0, 0, seeds_sr, edges_sr, emb_sr, W0, W1, sr_ent, sr_seed, N, E, S, smem);
    launch_graph(s1, 1, seeds_tg, edges_tg, emb_tg, W0, W1, tg_ent, tg_seed, N, E, S, smem);

    // join
    cudaEventRecord(evJoin, s1);
    cudaStreamWaitEvent(0, evJoin, 0);
}